// round 12
// baseline (speedup 1.0000x reference)
#include <cuda_runtime.h>
#include <cuda_fp16.h>
#include <cstdint>

#define SA 136           // smem stride (halves) for activations
#define SW 136           // smem stride (halves) for weights
#define NT 512           // 16 warps per CTA, 2 CTAs per SM
#define MROWS 64         // rows per CTA

#define B_ 512
#define LEAVES 1024
#define NINT 1023

// smem byte offsets (per CTA)
#define OFF_AH 0u
#define OFF_AL 17408u
#define OFF_W  34816u        // [Wh 128xSW | Wl 128xSW] single buffer
#define SMEM_TOTAL 104448    // 2 CTAs x 104448 = 208896 <= 227KB

// Weight storage (transposed [N][K], fp16 hi/lo split), filled by prep kernel
// leaf: L0 128x64=8192, L1..L4 4*16384, L5 40x128=5120  -> 78848
// int : L0 128x112=14336, L1..L4 4*16384, L5 40x128=5120 -> 84992
__device__ __align__(16) __half g_leaf_Wh[78848];
__device__ __align__(16) __half g_leaf_Wl[78848];
__device__ __align__(16) __half g_int_Wh[84992];
__device__ __align__(16) __half g_int_Wl[84992];
__device__ float  g_leaf_bias[768];
__device__ float  g_int_bias[768];

// Ping-pong activation buffers for the tree (fp32, 33 channels per node)
__device__ float g_curA[(size_t)B_ * LEAVES * 33];
__device__ float g_curB[(size_t)B_ * 512 * 33];

// ---------------------------------------------------------------------------
// Prep: convert & transpose all weights to fp16 hi/lo, pad, pack biases.
// ---------------------------------------------------------------------------
__global__ void prep_kernel(
    const float* __restrict__ lWin,  const float* __restrict__ lbin,
    const float* __restrict__ lWhid, const float* __restrict__ lbhid,
    const float* __restrict__ lWout, const float* __restrict__ lbout,
    const float* __restrict__ iWin,  const float* __restrict__ ibin,
    const float* __restrict__ iWhid, const float* __restrict__ ibhid,
    const float* __restrict__ iWout, const float* __restrict__ ibout)
{
    const int total = 78848 + 84992 + 1536;
    for (int i = blockIdx.x * blockDim.x + threadIdx.x; i < total;
         i += gridDim.x * blockDim.x) {
        if (i < 78848) {
            float v;
            if (i < 8192) {                 // L0: [128][64] <- lWin[k*128+n]
                int n = i >> 6, k = i & 63;
                v = lWin[k * 128 + n];
            } else if (i < 73728) {         // L1..L4: [128][128]
                int j = i - 8192;
                int l = j >> 14;
                int w = j & 16383;
                int n = w >> 7, k = w & 127;
                v = lWhid[l * 16384 + k * 128 + n];
            } else {                        // L5: [40][128] <- lWout[k*33+n]
                int j = i - 73728;
                int n = j >> 7, k = j & 127;
                v = (n < 33) ? lWout[k * 33 + n] : 0.f;
            }
            __half h = __float2half_rn(v);
            __half lo = __float2half_rn(v - __half2float(h));
            g_leaf_Wh[i] = h; g_leaf_Wl[i] = lo;
        } else if (i < 78848 + 84992) {
            int i2 = i - 78848;
            float v;
            if (i2 < 14336) {               // L0: [128][112] <- iWin[k*128+n], k<98
                int n = i2 / 112, k = i2 - n * 112;
                v = (k < 98) ? iWin[k * 128 + n] : 0.f;
            } else if (i2 < 79872) {
                int j = i2 - 14336;
                int l = j >> 14;
                int w = j & 16383;
                int n = w >> 7, k = w & 127;
                v = iWhid[l * 16384 + k * 128 + n];
            } else {
                int j = i2 - 79872;
                int n = j >> 7, k = j & 127;
                v = (n < 33) ? iWout[k * 33 + n] : 0.f;
            }
            __half h = __float2half_rn(v);
            __half lo = __float2half_rn(v - __half2float(h));
            g_int_Wh[i2] = h; g_int_Wl[i2] = lo;
        } else {
            int i3 = i - 78848 - 84992;     // 0..1535
            int j = (i3 < 768) ? i3 : i3 - 768;
            int l = j >> 7, c = j & 127;
            float v;
            if (i3 < 768) {
                if (l == 0)      v = lbin[c];
                else if (l < 5)  v = lbhid[(l - 1) * 128 + c];
                else             v = (c < 33) ? lbout[c] : 0.f;
                g_leaf_bias[j] = v;
            } else {
                if (l == 0)      v = ibin[c];
                else if (l < 5)  v = ibhid[(l - 1) * 128 + c];
                else             v = (c < 33) ? ibout[c] : 0.f;
                g_int_bias[j] = v;
            }
        }
    }
}

// ---------------------------------------------------------------------------
// PTX helpers
// ---------------------------------------------------------------------------
__device__ __forceinline__ void mma16816(float* c, const uint32_t* a,
                                         uint32_t b0, uint32_t b1)
{
    asm volatile(
        "mma.sync.aligned.m16n8k16.row.col.f32.f16.f16.f32 "
        "{%0,%1,%2,%3}, {%4,%5,%6,%7}, {%8,%9}, {%0,%1,%2,%3};\n"
        : "+f"(c[0]), "+f"(c[1]), "+f"(c[2]), "+f"(c[3])
        : "r"(a[0]), "r"(a[1]), "r"(a[2]), "r"(a[3]), "r"(b0), "r"(b1));
}

__device__ __forceinline__ void ldsm4(uint32_t* r, uint32_t addr)
{
    asm volatile("ldmatrix.sync.aligned.m8n8.x4.shared.b16 {%0,%1,%2,%3}, [%4];"
                 : "=r"(r[0]), "=r"(r[1]), "=r"(r[2]), "=r"(r[3]) : "r"(addr));
}

__device__ __forceinline__ void cpa16(uint32_t dst, const void* src)
{
    asm volatile("cp.async.cg.shared.global [%0], [%1], 16;" :: "r"(dst), "l"(src));
}
__device__ __forceinline__ void cpa_commit() { asm volatile("cp.async.commit_group;"); }

// stage one layer's weights (hi+lo) via cp.async into [Wh | Wl] buffer
__device__ __forceinline__ void stage_weights(
    uint32_t sbuf, const __half* gWh, const __half* gWl,
    int Np, int kv /* = Kp/8 */)
{
    const int Kp = kv << 3;
    const int nchunks = Np * kv;
    const uint32_t sWl = sbuf + 34816u;
    for (int i = threadIdx.x; i < nchunks; i += NT) {
        int r = i / kv;
        int c = (i - r * kv) << 3;
        uint32_t off = (uint32_t)(r * SW + c) * 2u;
        cpa16(sbuf + off, gWh + r * Kp + c);
        cpa16(sWl + off, gWl + r * Kp + c);
    }
}

// ---------------------------------------------------------------------------
// Run a 6-layer MLP for 64 rows held in smem (hi/lo split, 3-MMA fp32 emu).
// 16 warps: warp (wm 0..3, wn 0..3) owns a 16x32 tile. Single W buffer,
// staged for layer l+1 right after the post-MMA barrier (overlaps epilogue).
// Two such CTAs co-resident per SM interleave to hide barrier convoys.
// ---------------------------------------------------------------------------
__device__ __forceinline__ void run_unit(
    char* smem, const __half* gWh, const __half* gWl, const float* gbias,
    int Kp0, float* gout, float* dfinal, int row0)
{
    __half* sAh = (__half*)(smem + OFF_AH);
    __half* sAl = (__half*)(smem + OFF_AL);
    const uint32_t sb = (uint32_t)__cvta_generic_to_shared(smem);
    const uint32_t uAh = sb + OFF_AH;
    const uint32_t uAl = sb + OFF_AL;
    const uint32_t uWh = sb + OFF_W;
    const uint32_t uWl = uWh + 34816u;

    const int tid  = threadIdx.x;
    const int warp = tid >> 5;
    const int lane = tid & 31;
    const int wm = warp >> 2;      // 0..3 (16-row block)
    const int wn = warp & 3;       // 0..3 (32-col block)
    const int gid = lane >> 2;
    const int tig = lane & 3;

    const int aRow = wm * 16 + (lane & 15);
    const int aCol = (lane >> 4) << 3;
    const uint32_t offA0 = (uint32_t)(aRow * SA + aCol) * 2u;
    const int wRowBase = wn * 32 + ((lane >> 4) << 3) + (lane & 7);
    const int wCol = ((lane >> 3) & 1) << 3;
    const uint32_t offW0 = (uint32_t)(wRowBase * SW + wCol) * 2u;      // pair=0
    const uint32_t offW1 = offW0 + (uint32_t)(16 * SW) * 2u;           // pair=1

    const int KpA[6] = {Kp0, 128, 128, 128, 128, 128};
    const int NpA[6] = {128, 128, 128, 128, 128, 40};

    int woff = 128 * Kp0;
    #pragma unroll 1
    for (int l = 0; l < 6; ++l) {
        const int Kp = KpA[l];
        const int Np = NpA[l];

        // W(l) staged by caller (l=0) or previous iteration; make visible.
        asm volatile("cp.async.wait_group 0;");
        __syncthreads();

        int nt_count = (Np - wn * 32 + 7) >> 3;
        if (nt_count < 0) nt_count = 0;
        if (nt_count > 4) nt_count = 4;
        const int pair_count = (nt_count + 1) >> 1;

        float C[4][4];
        #pragma unroll
        for (int nt = 0; nt < 4; ++nt)
            #pragma unroll
            for (int q = 0; q < 4; ++q) C[nt][q] = 0.f;

        if (nt_count > 0) {
            uint32_t aAh0 = uAh + offA0;
            uint32_t aAl0 = uAl + offA0;
            uint32_t aWh0 = uWh + offW0, aWh1 = uWh + offW1;
            uint32_t aWl0 = uWl + offW0, aWl1 = uWl + offW1;

            for (int k0 = 0; k0 < Kp; k0 += 16) {
                uint32_t ah[4], al[4];
                uint32_t whf[2][4], wlf[2][4];
                ldsm4(ah, aAh0);
                ldsm4(al, aAl0);
                ldsm4(whf[0], aWh0); ldsm4(wlf[0], aWl0);
                if (pair_count > 1) { ldsm4(whf[1], aWh1); ldsm4(wlf[1], aWl1); }

                #pragma unroll
                for (int nt = 0; nt < 4; ++nt) {
                    if (nt < nt_count) {
                        const int p = nt >> 1, q = (nt & 1) << 1;
                        uint32_t b0h = whf[p][q], b1h = whf[p][q + 1];
                        uint32_t b0l = wlf[p][q], b1l = wlf[p][q + 1];
                        mma16816(C[nt], ah, b0h, b1h);
                        mma16816(C[nt], ah, b0l, b1l);
                        mma16816(C[nt], al, b0h, b1h);
                    }
                }
                aAh0 += 32; aAl0 += 32;
                aWh0 += 32; aWh1 += 32; aWl0 += 32; aWl1 += 32;
            }
        }
        __syncthreads();      // all MMA reads of A and W done

        // stage next layer's weights now; overlaps the epilogue below
        if (l < 5) {
            stage_weights(uWh, gWh + woff, gWl + woff,
                          NpA[l + 1], KpA[l + 1] >> 3);
            cpa_commit();
            woff += NpA[l + 1] * KpA[l + 1];
        } else {
            cpa_commit();     // empty group keeps loop-head wait trivial
        }

        // ---- epilogue ----
        if (l < 5) {
            #pragma unroll
            for (int nt = 0; nt < 4; ++nt) {
                if (nt < nt_count) {
                    int r  = wm * 16 + gid;
                    int cb = wn * 32 + nt * 8 + tig * 2;
                    float bb0 = gbias[l * 128 + cb];
                    float bb1 = gbias[l * 128 + cb + 1];
                    float v00 = fmaxf(C[nt][0] + bb0, 0.f);
                    float v01 = fmaxf(C[nt][1] + bb1, 0.f);
                    float v10 = fmaxf(C[nt][2] + bb0, 0.f);
                    float v11 = fmaxf(C[nt][3] + bb1, 0.f);
                    __half h00 = __float2half_rn(v00), h01 = __float2half_rn(v01);
                    __half h10 = __float2half_rn(v10), h11 = __float2half_rn(v11);
                    __half e00 = __float2half_rn(v00 - __half2float(h00));
                    __half e01 = __float2half_rn(v01 - __half2float(h01));
                    __half e10 = __float2half_rn(v10 - __half2float(h10));
                    __half e11 = __float2half_rn(v11 - __half2float(h11));
                    *(__half2*)(sAh + r * SA + cb)        = __halves2half2(h00, h01);
                    *(__half2*)(sAh + (r + 8) * SA + cb)  = __halves2half2(h10, h11);
                    *(__half2*)(sAl + r * SA + cb)        = __halves2half2(e00, e01);
                    *(__half2*)(sAl + (r + 8) * SA + cb)  = __halves2half2(e10, e11);
                }
            }
        } else {
            #pragma unroll
            for (int nt = 0; nt < 4; ++nt) {
                if (nt < nt_count) {
                    int r  = wm * 16 + gid;
                    int cb = wn * 32 + nt * 8 + tig * 2;
                    float bb0 = gbias[640 + cb];
                    float bb1 = gbias[640 + cb + 1];
                    float v00 = C[nt][0] + bb0;
                    float v01 = C[nt][1] + bb1;
                    float v10 = C[nt][2] + bb0;
                    float v11 = C[nt][3] + bb1;
                    if (dfinal) {
                        if (cb == 0) {
                            dfinal[row0 + r]     = v00;
                            dfinal[row0 + r + 8] = v10;
                        }
                    } else {
                        size_t ro = (size_t)(row0 + r) * 33;
                        size_t r8 = (size_t)(row0 + r + 8) * 33;
                        if (cb < 33)     { gout[ro + cb]     = v00; gout[r8 + cb]     = v10; }
                        if (cb + 1 < 33) { gout[ro + cb + 1] = v01; gout[r8 + cb + 1] = v11; }
                    }
                }
            }
        }
    }
}

// ---------------------------------------------------------------------------
// Leaf kernel: 64 rows/CTA of leaf_feat (K0=64) -> cur (33 ch, fp32)
// ---------------------------------------------------------------------------
__global__ void __launch_bounds__(NT, 2)
leaf_kernel(const float* __restrict__ leaf_feat, float* __restrict__ curOut)
{
    extern __shared__ char smem[];
    __half* sAh = (__half*)(smem + OFF_AH);
    __half* sAl = (__half*)(smem + OFF_AL);
    const uint32_t sb = (uint32_t)__cvta_generic_to_shared(smem);

    const int row0 = blockIdx.x * MROWS;

    // stage layer-0 weights first (overlaps A build)
    stage_weights(sb + OFF_W, g_leaf_Wh, g_leaf_Wl, 128, 8);
    cpa_commit();

    for (int i = threadIdx.x; i < MROWS * 16; i += NT) {
        int r = i >> 4, c4 = i & 15;
        float4 v = ((const float4*)(leaf_feat + (size_t)(row0 + r) * 64))[c4];
        int c = c4 * 4;
        __half h0 = __float2half_rn(v.x), h1 = __float2half_rn(v.y);
        __half h2 = __float2half_rn(v.z), h3 = __float2half_rn(v.w);
        __half e0 = __float2half_rn(v.x - __half2float(h0));
        __half e1 = __float2half_rn(v.y - __half2float(h1));
        __half e2 = __float2half_rn(v.z - __half2float(h2));
        __half e3 = __float2half_rn(v.w - __half2float(h3));
        *(__half2*)(sAh + r * SA + c)     = __halves2half2(h0, h1);
        *(__half2*)(sAh + r * SA + c + 2) = __halves2half2(h2, h3);
        *(__half2*)(sAl + r * SA + c)     = __halves2half2(e0, e1);
        *(__half2*)(sAl + r * SA + c + 2) = __halves2half2(e2, e3);
    }

    run_unit(smem, g_leaf_Wh, g_leaf_Wl, g_leaf_bias, 64, curOut, nullptr, row0);
}

// ---------------------------------------------------------------------------
// Tree-level kernel: builds [feat(32) | child0(33) | child1(33) | pad] rows
// ---------------------------------------------------------------------------
__global__ void __launch_bounds__(NT, 2)
int_kernel(const float* __restrict__ int_feat, const float* __restrict__ prev,
           float* __restrict__ curOut, int log2n, float* dfinal)
{
    extern __shared__ char smem[];
    __half* sAh = (__half*)(smem + OFF_AH);
    __half* sAl = (__half*)(smem + OFF_AL);
    const uint32_t sb = (uint32_t)__cvta_generic_to_shared(smem);

    const int row0 = blockIdx.x * MROWS;
    const int n = 1 << log2n;

    // stage layer-0 weights first (overlaps A build)
    stage_weights(sb + OFF_W, g_int_Wh, g_int_Wl, 128, 14);
    cpa_commit();

    for (int i = threadIdx.x; i < MROWS * 112; i += NT) {
        int r = i / 112, c = i - r * 112;
        int rowg = row0 + r;
        int b  = rowg >> log2n;
        int ii = rowg & (n - 1);
        float v;
        if (c < 32) {
            v = int_feat[((size_t)b * NINT + (n - 1) + ii) * 32 + c];
        } else if (c < 98) {
            v = prev[((size_t)b * (n << 1) + (ii << 1)) * 33 + (c - 32)];
        } else {
            v = 0.f;
        }
        __half h = __float2half_rn(v);
        __half e = __float2half_rn(v - __half2float(h));
        sAh[r * SA + c] = h;
        sAl[r * SA + c] = e;
    }

    run_unit(smem, g_int_Wh, g_int_Wl, g_int_bias, 112, curOut, dfinal, row0);
}

// ---------------------------------------------------------------------------
extern "C" void kernel_launch(void* const* d_in, const int* in_sizes, int n_in,
                              void* d_out, int out_size)
{
    const float* leaf_feat = (const float*)d_in[0];
    const float* int_feat  = (const float*)d_in[1];
    const float* lWin  = (const float*)d_in[2];
    const float* lbin  = (const float*)d_in[3];
    const float* lWhid = (const float*)d_in[4];
    const float* lbhid = (const float*)d_in[5];
    const float* lWout = (const float*)d_in[6];
    const float* lbout = (const float*)d_in[7];
    const float* iWin  = (const float*)d_in[8];
    const float* ibin  = (const float*)d_in[9];
    const float* iWhid = (const float*)d_in[10];
    const float* ibhid = (const float*)d_in[11];
    const float* iWout = (const float*)d_in[12];
    const float* ibout = (const float*)d_in[13];
    float* out = (float*)d_out;

    cudaFuncSetAttribute(leaf_kernel, cudaFuncAttributeMaxDynamicSharedMemorySize, SMEM_TOTAL);
    cudaFuncSetAttribute(int_kernel,  cudaFuncAttributeMaxDynamicSharedMemorySize, SMEM_TOTAL);

    float *curA = nullptr, *curB = nullptr;
    cudaGetSymbolAddress((void**)&curA, g_curA);
    cudaGetSymbolAddress((void**)&curB, g_curB);

    prep_kernel<<<256, 256>>>(lWin, lbin, lWhid, lbhid, lWout, lbout,
                              iWin, ibin, iWhid, ibhid, iWout, ibout);

    leaf_kernel<<<(B_ * LEAVES) / MROWS, NT, SMEM_TOTAL>>>(leaf_feat, curA);

    float* pin = curA;
    float* pout = curB;
    for (int d = 9; d >= 1; --d) {
        int rows = B_ << d;
        int_kernel<<<rows / MROWS, NT, SMEM_TOTAL>>>(int_feat, pin, pout, d, nullptr);
        float* t = pin; pin = pout; pout = t;
    }
    int_kernel<<<B_ / MROWS, NT, SMEM_TOTAL>>>(int_feat, pin, pout, 0, out);
}

// round 13
// speedup vs baseline: 1.6607x; 1.6607x over previous
#include <cuda_runtime.h>
#include <cuda_fp16.h>
#include <cstdint>

#define SA 136           // smem stride (halves) for activations
#define SW 136           // smem stride (halves) for weights
#define NT 1024          // 32 warps

#define B_ 512
#define LEAVES 1024
#define NINT 1023

// Weight storage (transposed [N][K], fp16 hi/lo split), filled by prep kernel
__device__ __align__(16) __half g_leaf_Wh[78848];
__device__ __align__(16) __half g_leaf_Wl[78848];
__device__ __align__(16) __half g_int_Wh[84992];
__device__ __align__(16) __half g_int_Wl[84992];
__device__ float  g_leaf_bias[768];
__device__ float  g_int_bias[768];

// Ping-pong activation buffers for the tree (fp32, 33 channels per node)
__device__ float g_curA[(size_t)B_ * LEAVES * 33];
__device__ float g_curB[(size_t)B_ * 512 * 33];

// ---------------------------------------------------------------------------
// Prep: convert & transpose all weights to fp16 hi/lo, pad, pack biases.
// ---------------------------------------------------------------------------
__global__ void prep_kernel(
    const float* __restrict__ lWin,  const float* __restrict__ lbin,
    const float* __restrict__ lWhid, const float* __restrict__ lbhid,
    const float* __restrict__ lWout, const float* __restrict__ lbout,
    const float* __restrict__ iWin,  const float* __restrict__ ibin,
    const float* __restrict__ iWhid, const float* __restrict__ ibhid,
    const float* __restrict__ iWout, const float* __restrict__ ibout)
{
    const int total = 78848 + 84992 + 1536;
    for (int i = blockIdx.x * blockDim.x + threadIdx.x; i < total;
         i += gridDim.x * blockDim.x) {
        if (i < 78848) {
            float v;
            if (i < 8192) {
                int n = i >> 6, k = i & 63;
                v = lWin[k * 128 + n];
            } else if (i < 73728) {
                int j = i - 8192;
                int l = j >> 14;
                int w = j & 16383;
                int n = w >> 7, k = w & 127;
                v = lWhid[l * 16384 + k * 128 + n];
            } else {
                int j = i - 73728;
                int n = j >> 7, k = j & 127;
                v = (n < 33) ? lWout[k * 33 + n] : 0.f;
            }
            __half h = __float2half_rn(v);
            __half lo = __float2half_rn(v - __half2float(h));
            g_leaf_Wh[i] = h; g_leaf_Wl[i] = lo;
        } else if (i < 78848 + 84992) {
            int i2 = i - 78848;
            float v;
            if (i2 < 14336) {
                int n = i2 / 112, k = i2 - n * 112;
                v = (k < 98) ? iWin[k * 128 + n] : 0.f;
            } else if (i2 < 79872) {
                int j = i2 - 14336;
                int l = j >> 14;
                int w = j & 16383;
                int n = w >> 7, k = w & 127;
                v = iWhid[l * 16384 + k * 128 + n];
            } else {
                int j = i2 - 79872;
                int n = j >> 7, k = j & 127;
                v = (n < 33) ? iWout[k * 33 + n] : 0.f;
            }
            __half h = __float2half_rn(v);
            __half lo = __float2half_rn(v - __half2float(h));
            g_int_Wh[i2] = h; g_int_Wl[i2] = lo;
        } else {
            int i3 = i - 78848 - 84992;
            int j = (i3 < 768) ? i3 : i3 - 768;
            int l = j >> 7, c = j & 127;
            float v;
            if (i3 < 768) {
                if (l == 0)      v = lbin[c];
                else if (l < 5)  v = lbhid[(l - 1) * 128 + c];
                else             v = (c < 33) ? lbout[c] : 0.f;
                g_leaf_bias[j] = v;
            } else {
                if (l == 0)      v = ibin[c];
                else if (l < 5)  v = ibhid[(l - 1) * 128 + c];
                else             v = (c < 33) ? ibout[c] : 0.f;
                g_int_bias[j] = v;
            }
        }
    }
}

// ---------------------------------------------------------------------------
// PTX helpers
// ---------------------------------------------------------------------------
__device__ __forceinline__ void mma16816(float* c, const uint32_t* a,
                                         uint32_t b0, uint32_t b1)
{
    asm volatile(
        "mma.sync.aligned.m16n8k16.row.col.f32.f16.f16.f32 "
        "{%0,%1,%2,%3}, {%4,%5,%6,%7}, {%8,%9}, {%0,%1,%2,%3};\n"
        : "+f"(c[0]), "+f"(c[1]), "+f"(c[2]), "+f"(c[3])
        : "r"(a[0]), "r"(a[1]), "r"(a[2]), "r"(a[3]), "r"(b0), "r"(b1));
}

__device__ __forceinline__ void ldsm4(uint32_t* r, uint32_t addr)
{
    asm volatile("ldmatrix.sync.aligned.m8n8.x4.shared.b16 {%0,%1,%2,%3}, [%4];"
                 : "=r"(r[0]), "=r"(r[1]), "=r"(r[2]), "=r"(r[3]) : "r"(addr));
}

__device__ __forceinline__ void cpa16(uint32_t dst, const void* src)
{
    asm volatile("cp.async.cg.shared.global [%0], [%1], 16;" :: "r"(dst), "l"(src));
}
__device__ __forceinline__ void cpa_commit() { asm volatile("cp.async.commit_group;"); }

// stage one layer's weights (hi+lo) via cp.async; KV, NP compile-time
template<int KV, int NP>
__device__ __forceinline__ void stage_weights(
    uint32_t sWh, uint32_t sWl, const __half* gWh, const __half* gWl)
{
    const int Kp = KV << 3;
    const int nchunks = NP * KV;
    #pragma unroll
    for (int base = 0; base < nchunks; base += NT) {
        int i = base + threadIdx.x;
        if (base + NT <= nchunks || i < nchunks) {
            int r = i / KV;
            int c = (i - r * KV) << 3;
            uint32_t off = (uint32_t)(r * SW + c) * 2u;
            cpa16(sWh + off, gWh + r * Kp + c);
            cpa16(sWl + off, gWl + r * Kp + c);
        }
    }
}

// ---------------------------------------------------------------------------
// One layer's MMA accumulation with literal trip counts.
// ---------------------------------------------------------------------------
template<int KSTEPS, int NTC>
__device__ __forceinline__ void mma_layer(
    float (&C)[4][4],
    uint32_t aAh0, uint32_t aAl0,
    uint32_t aWh0, uint32_t aWh1, uint32_t aWl0, uint32_t aWl1)
{
    #pragma unroll
    for (int ks = 0; ks < KSTEPS; ++ks) {
        uint32_t ah[4], al[4];
        uint32_t whf[2][4], wlf[2][4];
        ldsm4(ah, aAh0 + ks * 32u);
        ldsm4(al, aAl0 + ks * 32u);
        ldsm4(whf[0], aWh0 + ks * 32u);
        ldsm4(wlf[0], aWl0 + ks * 32u);
        if (NTC > 2) { ldsm4(whf[1], aWh1 + ks * 32u); ldsm4(wlf[1], aWl1 + ks * 32u); }

        #pragma unroll
        for (int nt = 0; nt < 4; ++nt) {
            if (nt < NTC) {
                const int p = nt >> 1, q = (nt & 1) << 1;
                uint32_t b0h = whf[p][q], b1h = whf[p][q + 1];
                uint32_t b0l = wlf[p][q], b1l = wlf[p][q + 1];
                mma16816(C[nt], ah, b0h, b1h);
                mma16816(C[nt], ah, b0l, b1l);
                mma16816(C[nt], al, b0h, b1h);
            }
        }
    }
}

// ---------------------------------------------------------------------------
// 6-layer MLP for 128 rows in smem. 32 warps, m16n32 warp tiles, double-
// buffered weights. All trip counts compile-time.
// ---------------------------------------------------------------------------
template<int KP0>
__device__ __forceinline__ void run_unit(
    __half* smem, const __half* gWh, const __half* gWl, const float* gbias,
    float* gout, float* dfinal, int row0)
{
    __half* sAh = smem;
    __half* sAl = smem + 17408;
    const uint32_t smem_u = (uint32_t)__cvta_generic_to_shared(smem);
    const uint32_t uAh = smem_u;
    const uint32_t uAl = smem_u + 17408u * 2u;
    const uint32_t uW0 = smem_u + 34816u * 2u;
    const uint32_t uW1 = smem_u + 69632u * 2u;

    const int tid  = threadIdx.x;
    const int warp = tid >> 5;
    const int lane = tid & 31;
    const int wm = warp >> 2;
    const int wn = warp & 3;
    const int gid = lane >> 2;
    const int tig = lane & 3;

    const int aRow = wm * 16 + (lane & 15);
    const int aCol = (lane >> 4) << 3;
    const uint32_t offA0 = (uint32_t)(aRow * SA + aCol) * 2u;
    const int wRowBase = wn * 32 + ((lane >> 4) << 3) + (lane & 7);
    const int wCol = ((lane >> 3) & 1) << 3;
    const uint32_t offW0 = (uint32_t)(wRowBase * SW + wCol) * 2u;
    const uint32_t offW1 = offW0 + (uint32_t)(16 * SW) * 2u;

    stage_weights<KP0 / 8, 128>(uW0, uW0 + 17408u * 2u, gWh, gWl);
    cpa_commit();

    int woff = 128 * KP0;
    #pragma unroll
    for (int l = 0; l < 6; ++l) {
        const uint32_t uWbuf = (l & 1) ? uW1 : uW0;
        const uint32_t uWh = uWbuf;
        const uint32_t uWl = uWbuf + 17408u * 2u;

        if (l < 5) {
            const uint32_t uNext = (l & 1) ? uW0 : uW1;
            if (l < 4)
                stage_weights<16, 128>(uNext, uNext + 17408u * 2u,
                                       gWh + woff, gWl + woff);
            else
                stage_weights<16, 40>(uNext, uNext + 17408u * 2u,
                                      gWh + woff, gWl + woff);
            cpa_commit();
            woff += ((l < 4) ? 128 : 40) * 128;
            asm volatile("cp.async.wait_group 1;");
        } else {
            asm volatile("cp.async.wait_group 0;");
        }
        __syncthreads();

        float C[4][4];
        #pragma unroll
        for (int nt = 0; nt < 4; ++nt)
            #pragma unroll
            for (int q = 0; q < 4; ++q) C[nt][q] = 0.f;

        int ntc = 4;
        if (l == 0) {
            mma_layer<KP0 / 16, 4>(C, uAh + offA0, uAl + offA0,
                                   uWh + offW0, uWh + offW1,
                                   uWl + offW0, uWl + offW1);
        } else if (l < 5) {
            mma_layer<8, 4>(C, uAh + offA0, uAl + offA0,
                            uWh + offW0, uWh + offW1,
                            uWl + offW0, uWl + offW1);
        } else {
            ntc = (40 - wn * 32 + 7) >> 3;
            if (ntc < 0) ntc = 0;
            if (ntc > 4) ntc = 4;
            if (ntc >= 3)
                mma_layer<8, 4>(C, uAh + offA0, uAl + offA0,
                                uWh + offW0, uWh + offW1,
                                uWl + offW0, uWl + offW1);
            else if (ntc >= 1)
                mma_layer<8, 2>(C, uAh + offA0, uAl + offA0,
                                uWh + offW0, uWh + offW1,
                                uWl + offW0, uWl + offW1);
        }
        __syncthreads();

        if (l < 5) {
            #pragma unroll
            for (int nt = 0; nt < 4; ++nt) {
                int r  = wm * 16 + gid;
                int cb = wn * 32 + nt * 8 + tig * 2;
                float bb0 = gbias[l * 128 + cb];
                float bb1 = gbias[l * 128 + cb + 1];
                float v00 = fmaxf(C[nt][0] + bb0, 0.f);
                float v01 = fmaxf(C[nt][1] + bb1, 0.f);
                float v10 = fmaxf(C[nt][2] + bb0, 0.f);
                float v11 = fmaxf(C[nt][3] + bb1, 0.f);
                __half h00 = __float2half_rn(v00), h01 = __float2half_rn(v01);
                __half h10 = __float2half_rn(v10), h11 = __float2half_rn(v11);
                __half e00 = __float2half_rn(v00 - __half2float(h00));
                __half e01 = __float2half_rn(v01 - __half2float(h01));
                __half e10 = __float2half_rn(v10 - __half2float(h10));
                __half e11 = __float2half_rn(v11 - __half2float(h11));
                *(__half2*)(sAh + r * SA + cb)        = __halves2half2(h00, h01);
                *(__half2*)(sAh + (r + 8) * SA + cb)  = __halves2half2(h10, h11);
                *(__half2*)(sAl + r * SA + cb)        = __halves2half2(e00, e01);
                *(__half2*)(sAl + (r + 8) * SA + cb)  = __halves2half2(e10, e11);
            }
        } else {
            #pragma unroll
            for (int nt = 0; nt < 4; ++nt) {
                if (nt < ntc) {
                    int r  = wm * 16 + gid;
                    int cb = wn * 32 + nt * 8 + tig * 2;
                    float bb0 = gbias[640 + cb];
                    float bb1 = gbias[640 + cb + 1];
                    float v00 = C[nt][0] + bb0;
                    float v01 = C[nt][1] + bb1;
                    float v10 = C[nt][2] + bb0;
                    float v11 = C[nt][3] + bb1;
                    if (dfinal) {
                        if (cb == 0) {
                            dfinal[row0 + r]     = v00;
                            dfinal[row0 + r + 8] = v10;
                        }
                    } else {
                        size_t ro = (size_t)(row0 + r) * 33;
                        size_t r8 = (size_t)(row0 + r + 8) * 33;
                        if (cb < 33)     { gout[ro + cb]     = v00; gout[r8 + cb]     = v10; }
                        if (cb + 1 < 33) { gout[ro + cb + 1] = v01; gout[r8 + cb + 1] = v11; }
                    }
                }
            }
        }
    }
}

// ---------------------------------------------------------------------------
__global__ void __launch_bounds__(NT, 1)
leaf_kernel(const float* __restrict__ leaf_feat, float* __restrict__ curOut)
{
    extern __shared__ __half smem[];
    __half* sAh = smem;
    __half* sAl = smem + 17408;

    const int row0 = blockIdx.x * 128;

    for (int i = threadIdx.x; i < 128 * 16; i += NT) {
        int r = i >> 4, c4 = i & 15;
        float4 v = ((const float4*)(leaf_feat + (size_t)(row0 + r) * 64))[c4];
        int c = c4 * 4;
        __half h0 = __float2half_rn(v.x), h1 = __float2half_rn(v.y);
        __half h2 = __float2half_rn(v.z), h3 = __float2half_rn(v.w);
        __half e0 = __float2half_rn(v.x - __half2float(h0));
        __half e1 = __float2half_rn(v.y - __half2float(h1));
        __half e2 = __float2half_rn(v.z - __half2float(h2));
        __half e3 = __float2half_rn(v.w - __half2float(h3));
        *(__half2*)(sAh + r * SA + c)     = __halves2half2(h0, h1);
        *(__half2*)(sAh + r * SA + c + 2) = __halves2half2(h2, h3);
        *(__half2*)(sAl + r * SA + c)     = __halves2half2(e0, e1);
        *(__half2*)(sAl + r * SA + c + 2) = __halves2half2(e2, e3);
    }

    run_unit<64>(smem, g_leaf_Wh, g_leaf_Wl, g_leaf_bias, curOut, nullptr, row0);
}

// ---------------------------------------------------------------------------
__global__ void __launch_bounds__(NT, 1)
int_kernel(const float* __restrict__ int_feat, const float* __restrict__ prev,
           float* __restrict__ curOut, int log2n, float* dfinal)
{
    extern __shared__ __half smem[];
    __half* sAh = smem;
    __half* sAl = smem + 17408;

    const int row0 = blockIdx.x * 128;
    const int n = 1 << log2n;

    for (int i = threadIdx.x; i < 128 * 112; i += NT) {
        int r = i / 112, c = i - r * 112;
        int rowg = row0 + r;
        int b  = rowg >> log2n;
        int ii = rowg & (n - 1);
        float v;
        if (c < 32) {
            v = int_feat[((size_t)b * NINT + (n - 1) + ii) * 32 + c];
        } else if (c < 98) {
            v = prev[((size_t)b * (n << 1) + (ii << 1)) * 33 + (c - 32)];
        } else {
            v = 0.f;
        }
        __half h = __float2half_rn(v);
        __half e = __float2half_rn(v - __half2float(h));
        sAh[r * SA + c] = h;
        sAl[r * SA + c] = e;
    }

    run_unit<112>(smem, g_int_Wh, g_int_Wl, g_int_bias, curOut, dfinal, row0);
}

// ---------------------------------------------------------------------------
extern "C" void kernel_launch(void* const* d_in, const int* in_sizes, int n_in,
                              void* d_out, int out_size)
{
    const float* leaf_feat = (const float*)d_in[0];
    const float* int_feat  = (const float*)d_in[1];
    const float* lWin  = (const float*)d_in[2];
    const float* lbin  = (const float*)d_in[3];
    const float* lWhid = (const float*)d_in[4];
    const float* lbhid = (const float*)d_in[5];
    const float* lWout = (const float*)d_in[6];
    const float* lbout = (const float*)d_in[7];
    const float* iWin  = (const float*)d_in[8];
    const float* ibin  = (const float*)d_in[9];
    const float* iWhid = (const float*)d_in[10];
    const float* ibhid = (const float*)d_in[11];
    const float* iWout = (const float*)d_in[12];
    const float* ibout = (const float*)d_in[13];
    float* out = (float*)d_out;

    const int smem_bytes = (2 * 17408 + 2 * 34816) * (int)sizeof(__half); // 208896
    cudaFuncSetAttribute(leaf_kernel, cudaFuncAttributeMaxDynamicSharedMemorySize, smem_bytes);
    cudaFuncSetAttribute(int_kernel,  cudaFuncAttributeMaxDynamicSharedMemorySize, smem_bytes);

    float *curA = nullptr, *curB = nullptr;
    cudaGetSymbolAddress((void**)&curA, g_curA);
    cudaGetSymbolAddress((void**)&curB, g_curB);

    prep_kernel<<<256, 256>>>(lWin, lbin, lWhid, lbhid, lWout, lbout,
                              iWin, ibin, iWhid, ibhid, iWout, ibout);

    leaf_kernel<<<(B_ * LEAVES) / 128, NT, smem_bytes>>>(leaf_feat, curA);

    float* pin = curA;
    float* pout = curB;
    for (int d = 9; d >= 1; --d) {
        int rows = B_ << d;
        int_kernel<<<rows / 128, NT, smem_bytes>>>(int_feat, pin, pout, d, nullptr);
        float* t = pin; pin = pout; pout = t;
    }
    int_kernel<<<B_ / 128, NT, smem_bytes>>>(int_feat, pin, pout, 0, out);
}

// round 14
// speedup vs baseline: 1.6989x; 1.0230x over previous
#include <cuda_runtime.h>
#include <cuda_fp16.h>
#include <cstdint>

#define SA 136           // smem stride (halves) for activations (=17*8)
#define SW 136           // smem stride (halves) for weights
#define NT 1024          // 32 warps

#define B_ 512
#define LEAVES 1024
#define NINT 1023

// smem byte offsets
//   A hi: 0..34816, A lo: 34816..69632, W buf0: 69632, W buf1: 139264,
//   mbar0: 208896, mbar1: 208904
#define OFF_W0   69632u
#define OFF_W1   139264u
#define OFF_MB0  208896u
#define OFF_MB1  208904u
#define SMEM_TOTAL 208912
#define WIMG_BYTES 69632u        // one layer image: [Wh 128xSW | Wl 128xSW]
#define WIMG_HALVES 34816        // per layer, halves

// Weight images: 6 layers x [hi 17408 | lo 17408] halves, exact smem layout.
__device__ __align__(16) __half g_leaf_Wimg[6 * WIMG_HALVES];
__device__ __align__(16) __half g_int_Wimg[6 * WIMG_HALVES];
__device__ float g_leaf_bias[768];
__device__ float g_int_bias[768];

// Ping-pong activation buffers for the tree (fp32, 33 channels per node)
__device__ float g_curA[(size_t)B_ * LEAVES * 33];
__device__ float g_curB[(size_t)B_ * 512 * 33];

// ---------------------------------------------------------------------------
// Prep: bake per-layer smem weight images (hi/lo fp16, SW-stride) + biases.
// Each iteration handles one 8-half (16B) chunk of one image row.
// ---------------------------------------------------------------------------
__global__ void prep_kernel(
    const float* __restrict__ lWin,  const float* __restrict__ lbin,
    const float* __restrict__ lWhid, const float* __restrict__ lbhid,
    const float* __restrict__ lWout, const float* __restrict__ lbout,
    const float* __restrict__ iWin,  const float* __restrict__ ibin,
    const float* __restrict__ iWhid, const float* __restrict__ ibhid,
    const float* __restrict__ iWout, const float* __restrict__ ibout)
{
    // per unit: 6 layers x 2 mats x 128 rows x 17 chunks = 26112 chunks
    const int CHUNKS_PER_UNIT = 26112;
    const int NCHUNKS = 2 * CHUNKS_PER_UNIT;     // 52224
    const int total = NCHUNKS + 1536;
    for (int idx = blockIdx.x * blockDim.x + threadIdx.x; idx < total;
         idx += gridDim.x * blockDim.x) {
        if (idx < NCHUNKS) {
            const int unit = idx / CHUNKS_PER_UNIT;
            int j = idx - unit * CHUNKS_PER_UNIT;
            const int layer = j / 4352;  j -= layer * 4352;   // 2*128*17
            const int mat   = j / 2176;  j -= mat * 2176;     // 128*17
            const int n     = j / 17;
            const int c0    = (j - n * 17) * 8;

            __half out8[8];
            #pragma unroll
            for (int h = 0; h < 8; ++h) {
                const int k = c0 + h;
                float v = 0.f;
                if (k < 128) {
                    if (unit == 0) {
                        if (layer == 0)      v = (k < 64) ? lWin[k * 128 + n] : 0.f;
                        else if (layer < 5)  v = lWhid[(layer - 1) * 16384 + k * 128 + n];
                        else                 v = (n < 33) ? lWout[k * 33 + n] : 0.f;
                    } else {
                        if (layer == 0)      v = (k < 98) ? iWin[k * 128 + n] : 0.f;
                        else if (layer < 5)  v = iWhid[(layer - 1) * 16384 + k * 128 + n];
                        else                 v = (n < 33) ? iWout[k * 33 + n] : 0.f;
                    }
                }
                __half hi = __float2half_rn(v);
                out8[h] = (mat == 0) ? hi : __float2half_rn(v - __half2float(hi));
            }
            size_t off = (size_t)layer * WIMG_HALVES + (size_t)mat * 17408
                       + (size_t)n * SW + c0;
            __half* dst = (unit == 0) ? g_leaf_Wimg : g_int_Wimg;
            *(uint4*)(dst + off) = *(uint4*)out8;
        } else {
            int i3 = idx - NCHUNKS;              // 0..1535
            int j = (i3 < 768) ? i3 : i3 - 768;
            int l = j >> 7, c = j & 127;
            float v;
            if (i3 < 768) {
                if (l == 0)      v = lbin[c];
                else if (l < 5)  v = lbhid[(l - 1) * 128 + c];
                else             v = (c < 33) ? lbout[c] : 0.f;
                g_leaf_bias[j] = v;
            } else {
                if (l == 0)      v = ibin[c];
                else if (l < 5)  v = ibhid[(l - 1) * 128 + c];
                else             v = (c < 33) ? ibout[c] : 0.f;
                g_int_bias[j] = v;
            }
        }
    }
}

// ---------------------------------------------------------------------------
// PTX helpers
// ---------------------------------------------------------------------------
__device__ __forceinline__ void mma16816(float* c, const uint32_t* a,
                                         uint32_t b0, uint32_t b1)
{
    asm volatile(
        "mma.sync.aligned.m16n8k16.row.col.f32.f16.f16.f32 "
        "{%0,%1,%2,%3}, {%4,%5,%6,%7}, {%8,%9}, {%0,%1,%2,%3};\n"
        : "+f"(c[0]), "+f"(c[1]), "+f"(c[2]), "+f"(c[3])
        : "r"(a[0]), "r"(a[1]), "r"(a[2]), "r"(a[3]), "r"(b0), "r"(b1));
}

__device__ __forceinline__ void ldsm4(uint32_t* r, uint32_t addr)
{
    asm volatile("ldmatrix.sync.aligned.m8n8.x4.shared.b16 {%0,%1,%2,%3}, [%4];"
                 : "=r"(r[0]), "=r"(r[1]), "=r"(r[2]), "=r"(r[3]) : "r"(addr));
}

__device__ __forceinline__ void mbar_init(uint32_t mbar, uint32_t cnt)
{
    asm volatile("mbarrier.init.shared.b64 [%0], %1;" :: "r"(mbar), "r"(cnt) : "memory");
}
__device__ __forceinline__ void mbar_expect_tx(uint32_t mbar, uint32_t bytes)
{
    asm volatile("mbarrier.arrive.expect_tx.shared.b64 _, [%0], %1;"
                 :: "r"(mbar), "r"(bytes) : "memory");
}
__device__ __forceinline__ void bulk_g2s(uint32_t dst, const void* src,
                                         uint32_t bytes, uint32_t mbar)
{
    asm volatile(
        "cp.async.bulk.shared::cluster.global.mbarrier::complete_tx::bytes "
        "[%0], [%1], %2, [%3];"
        :: "r"(dst), "l"(src), "r"(bytes), "r"(mbar) : "memory");
}
__device__ __forceinline__ void mbar_wait(uint32_t mbar, uint32_t parity)
{
    asm volatile(
        "{\n\t.reg .pred P;\n\t"
        "WL%=:\n\t"
        "mbarrier.try_wait.parity.acquire.cta.shared::cta.b64 P, [%0], %1, 0x989680;\n\t"
        "@P bra.uni WD%=;\n\t"
        "bra.uni WL%=;\n\t"
        "WD%=:\n\t}"
        :: "r"(mbar), "r"(parity) : "memory");
}
#define FENCE_PROXY_ASYNC() asm volatile("fence.proxy.async.shared::cta;" ::: "memory")

// issue mbar init + first two layer images (call at kernel start, all threads)
__device__ __forceinline__ void stage_start(uint32_t sb, const __half* gWimg)
{
    if (threadIdx.x == 0) {
        mbar_init(sb + OFF_MB0, 1);
        mbar_init(sb + OFF_MB1, 1);
    }
    __syncthreads();
    if (threadIdx.x == 0) {
        mbar_expect_tx(sb + OFF_MB0, WIMG_BYTES);
        bulk_g2s(sb + OFF_W0, gWimg, WIMG_BYTES, sb + OFF_MB0);
        mbar_expect_tx(sb + OFF_MB1, WIMG_BYTES);
        bulk_g2s(sb + OFF_W1, gWimg + WIMG_HALVES, WIMG_BYTES, sb + OFF_MB1);
    }
}

// ---------------------------------------------------------------------------
// One layer's MMA accumulation with literal trip counts.
// ---------------------------------------------------------------------------
template<int KSTEPS, int NTC>
__device__ __forceinline__ void mma_layer(
    float (&C)[4][4],
    uint32_t aAh0, uint32_t aAl0,
    uint32_t aWh0, uint32_t aWh1, uint32_t aWl0, uint32_t aWl1)
{
    #pragma unroll
    for (int ks = 0; ks < KSTEPS; ++ks) {
        uint32_t ah[4], al[4];
        uint32_t whf[2][4], wlf[2][4];
        ldsm4(ah, aAh0 + ks * 32u);
        ldsm4(al, aAl0 + ks * 32u);
        ldsm4(whf[0], aWh0 + ks * 32u);
        ldsm4(wlf[0], aWl0 + ks * 32u);
        if (NTC > 2) { ldsm4(whf[1], aWh1 + ks * 32u); ldsm4(wlf[1], aWl1 + ks * 32u); }

        #pragma unroll
        for (int nt = 0; nt < 4; ++nt) {
            if (nt < NTC) {
                const int p = nt >> 1, q = (nt & 1) << 1;
                uint32_t b0h = whf[p][q], b1h = whf[p][q + 1];
                uint32_t b0l = wlf[p][q], b1l = wlf[p][q + 1];
                mma16816(C[nt], ah, b0h, b1h);
                mma16816(C[nt], ah, b0l, b1l);
                mma16816(C[nt], al, b0h, b1h);
            }
        }
    }
}

// ---------------------------------------------------------------------------
// 6-layer MLP for 128 rows in smem. 32 warps, m16n32 warp tiles.
// Weights arrive via ONE cp.async.bulk per layer (mbarrier completion),
// double-buffered; the bulk for layer l+2 is issued at layer l's tail.
// ---------------------------------------------------------------------------
template<int KP0>
__device__ __forceinline__ void run_unit(
    __half* smem, const __half* gWimg, const float* gbias,
    float* gout, float* dfinal, int row0)
{
    __half* sAh = smem;
    __half* sAl = smem + 17408;
    const uint32_t sb = (uint32_t)__cvta_generic_to_shared(smem);
    const uint32_t uAh = sb;
    const uint32_t uAl = sb + 34816u;

    const int tid  = threadIdx.x;
    const int warp = tid >> 5;
    const int lane = tid & 31;
    const int wm = warp >> 2;
    const int wn = warp & 3;
    const int gid = lane >> 2;
    const int tig = lane & 3;

    const int aRow = wm * 16 + (lane & 15);
    const int aCol = (lane >> 4) << 3;
    const uint32_t offA0 = (uint32_t)(aRow * SA + aCol) * 2u;
    const int wRowBase = wn * 32 + ((lane >> 4) << 3) + (lane & 7);
    const int wCol = ((lane >> 3) & 1) << 3;
    const uint32_t offW0 = (uint32_t)(wRowBase * SW + wCol) * 2u;
    const uint32_t offW1 = offW0 + (uint32_t)(16 * SW) * 2u;

    #pragma unroll
    for (int l = 0; l < 6; ++l) {
        const uint32_t uWh = sb + ((l & 1) ? OFF_W1 : OFF_W0);
        const uint32_t uWl = uWh + 34816u;
        const uint32_t mb  = sb + ((l & 1) ? OFF_MB1 : OFF_MB0);

        __syncthreads();                       // prev epilogue A-writes visible
        mbar_wait(mb, (uint32_t)((l >> 1) & 1));   // W(l) image arrived

        float C[4][4];
        #pragma unroll
        for (int nt = 0; nt < 4; ++nt)
            #pragma unroll
            for (int q = 0; q < 4; ++q) C[nt][q] = 0.f;

        int ntc = 4;
        if (l == 0) {
            mma_layer<KP0 / 16, 4>(C, uAh + offA0, uAl + offA0,
                                   uWh + offW0, uWh + offW1,
                                   uWl + offW0, uWl + offW1);
        } else if (l < 5) {
            mma_layer<8, 4>(C, uAh + offA0, uAl + offA0,
                            uWh + offW0, uWh + offW1,
                            uWl + offW0, uWl + offW1);
        } else {
            ntc = (40 - wn * 32 + 7) >> 3;
            if (ntc < 0) ntc = 0;
            if (ntc > 4) ntc = 4;
            if (ntc >= 3)
                mma_layer<8, 4>(C, uAh + offA0, uAl + offA0,
                                uWh + offW0, uWh + offW1,
                                uWl + offW0, uWl + offW1);
            else if (ntc >= 1)
                mma_layer<8, 2>(C, uAh + offA0, uAl + offA0,
                                uWh + offW0, uWh + offW1,
                                uWl + offW0, uWl + offW1);
        }
        __syncthreads();                       // all reads of A and W(l) done

        // issue bulk copy of W(l+2) into this buffer; overlaps epilogue+next MMA
        if (l < 4 && tid == 0) {
            FENCE_PROXY_ASYNC();
            mbar_expect_tx(mb, WIMG_BYTES);
            bulk_g2s(uWh, gWimg + (size_t)(l + 2) * WIMG_HALVES, WIMG_BYTES, mb);
        }

        // ---- epilogue ----
        if (l < 5) {
            #pragma unroll
            for (int nt = 0; nt < 4; ++nt) {
                int r  = wm * 16 + gid;
                int cb = wn * 32 + nt * 8 + tig * 2;
                float bb0 = gbias[l * 128 + cb];
                float bb1 = gbias[l * 128 + cb + 1];
                float v00 = fmaxf(C[nt][0] + bb0, 0.f);
                float v01 = fmaxf(C[nt][1] + bb1, 0.f);
                float v10 = fmaxf(C[nt][2] + bb0, 0.f);
                float v11 = fmaxf(C[nt][3] + bb1, 0.f);
                __half h00 = __float2half_rn(v00), h01 = __float2half_rn(v01);
                __half h10 = __float2half_rn(v10), h11 = __float2half_rn(v11);
                __half e00 = __float2half_rn(v00 - __half2float(h00));
                __half e01 = __float2half_rn(v01 - __half2float(h01));
                __half e10 = __float2half_rn(v10 - __half2float(h10));
                __half e11 = __float2half_rn(v11 - __half2float(h11));
                *(__half2*)(sAh + r * SA + cb)        = __halves2half2(h00, h01);
                *(__half2*)(sAh + (r + 8) * SA + cb)  = __halves2half2(h10, h11);
                *(__half2*)(sAl + r * SA + cb)        = __halves2half2(e00, e01);
                *(__half2*)(sAl + (r + 8) * SA + cb)  = __halves2half2(e10, e11);
            }
        } else {
            #pragma unroll
            for (int nt = 0; nt < 4; ++nt) {
                if (nt < ntc) {
                    int r  = wm * 16 + gid;
                    int cb = wn * 32 + nt * 8 + tig * 2;
                    float bb0 = gbias[640 + cb];
                    float bb1 = gbias[640 + cb + 1];
                    float v00 = C[nt][0] + bb0;
                    float v01 = C[nt][1] + bb1;
                    float v10 = C[nt][2] + bb0;
                    float v11 = C[nt][3] + bb1;
                    if (dfinal) {
                        if (cb == 0) {
                            dfinal[row0 + r]     = v00;
                            dfinal[row0 + r + 8] = v10;
                        }
                    } else {
                        size_t ro = (size_t)(row0 + r) * 33;
                        size_t r8 = (size_t)(row0 + r + 8) * 33;
                        if (cb < 33)     { gout[ro + cb]     = v00; gout[r8 + cb]     = v10; }
                        if (cb + 1 < 33) { gout[ro + cb + 1] = v01; gout[r8 + cb + 1] = v11; }
                    }
                }
            }
        }
    }
}

// ---------------------------------------------------------------------------
__global__ void __launch_bounds__(NT, 1)
leaf_kernel(const float* __restrict__ leaf_feat, float* __restrict__ curOut)
{
    extern __shared__ __half smem[];
    __half* sAh = smem;
    __half* sAl = smem + 17408;
    const uint32_t sb = (uint32_t)__cvta_generic_to_shared(smem);

    stage_start(sb, g_leaf_Wimg);    // overlaps with A build below

    const int row0 = blockIdx.x * 128;

    for (int i = threadIdx.x; i < 128 * 16; i += NT) {
        int r = i >> 4, c4 = i & 15;
        float4 v = ((const float4*)(leaf_feat + (size_t)(row0 + r) * 64))[c4];
        int c = c4 * 4;
        __half h0 = __float2half_rn(v.x), h1 = __float2half_rn(v.y);
        __half h2 = __float2half_rn(v.z), h3 = __float2half_rn(v.w);
        __half e0 = __float2half_rn(v.x - __half2float(h0));
        __half e1 = __float2half_rn(v.y - __half2float(h1));
        __half e2 = __float2half_rn(v.z - __half2float(h2));
        __half e3 = __float2half_rn(v.w - __half2float(h3));
        *(__half2*)(sAh + r * SA + c)     = __halves2half2(h0, h1);
        *(__half2*)(sAh + r * SA + c + 2) = __halves2half2(h2, h3);
        *(__half2*)(sAl + r * SA + c)     = __halves2half2(e0, e1);
        *(__half2*)(sAl + r * SA + c + 2) = __halves2half2(e2, e3);
    }

    run_unit<64>(smem, g_leaf_Wimg, g_leaf_bias, curOut, nullptr, row0);
}

// ---------------------------------------------------------------------------
__global__ void __launch_bounds__(NT, 1)
int_kernel(const float* __restrict__ int_feat, const float* __restrict__ prev,
           float* __restrict__ curOut, int log2n, float* dfinal)
{
    extern __shared__ __half smem[];
    __half* sAh = smem;
    __half* sAl = smem + 17408;
    const uint32_t sb = (uint32_t)__cvta_generic_to_shared(smem);

    stage_start(sb, g_int_Wimg);     // overlaps with A build below

    const int row0 = blockIdx.x * 128;
    const int n = 1 << log2n;

    for (int i = threadIdx.x; i < 128 * 112; i += NT) {
        int r = i / 112, c = i - r * 112;
        int rowg = row0 + r;
        int b  = rowg >> log2n;
        int ii = rowg & (n - 1);
        float v;
        if (c < 32) {
            v = int_feat[((size_t)b * NINT + (n - 1) + ii) * 32 + c];
        } else if (c < 98) {
            v = prev[((size_t)b * (n << 1) + (ii << 1)) * 33 + (c - 32)];
        } else {
            v = 0.f;
        }
        __half h = __float2half_rn(v);
        __half e = __float2half_rn(v - __half2float(h));
        sAh[r * SA + c] = h;
        sAl[r * SA + c] = e;
    }

    run_unit<112>(smem, g_int_Wimg, g_int_bias, curOut, dfinal, row0);
}

// ---------------------------------------------------------------------------
extern "C" void kernel_launch(void* const* d_in, const int* in_sizes, int n_in,
                              void* d_out, int out_size)
{
    const float* leaf_feat = (const float*)d_in[0];
    const float* int_feat  = (const float*)d_in[1];
    const float* lWin  = (const float*)d_in[2];
    const float* lbin  = (const float*)d_in[3];
    const float* lWhid = (const float*)d_in[4];
    const float* lbhid = (const float*)d_in[5];
    const float* lWout = (const float*)d_in[6];
    const float* lbout = (const float*)d_in[7];
    const float* iWin  = (const float*)d_in[8];
    const float* ibin  = (const float*)d_in[9];
    const float* iWhid = (const float*)d_in[10];
    const float* ibhid = (const float*)d_in[11];
    const float* iWout = (const float*)d_in[12];
    const float* ibout = (const float*)d_in[13];
    float* out = (float*)d_out;

    cudaFuncSetAttribute(leaf_kernel, cudaFuncAttributeMaxDynamicSharedMemorySize, SMEM_TOTAL);
    cudaFuncSetAttribute(int_kernel,  cudaFuncAttributeMaxDynamicSharedMemorySize, SMEM_TOTAL);

    float *curA = nullptr, *curB = nullptr;
    cudaGetSymbolAddress((void**)&curA, g_curA);
    cudaGetSymbolAddress((void**)&curB, g_curB);

    prep_kernel<<<256, 256>>>(lWin, lbin, lWhid, lbhid, lWout, lbout,
                              iWin, ibin, iWhid, ibhid, iWout, ibout);

    leaf_kernel<<<(B_ * LEAVES) / 128, NT, SMEM_TOTAL>>>(leaf_feat, curA);

    float* pin = curA;
    float* pout = curB;
    for (int d = 9; d >= 1; --d) {
        int rows = B_ << d;
        int_kernel<<<rows / 128, NT, SMEM_TOTAL>>>(int_feat, pin, pout, d, nullptr);
        float* t = pin; pin = pout; pout = t;
    }
    int_kernel<<<B_ / 128, NT, SMEM_TOTAL>>>(int_feat, pin, pout, 0, out);
}